// round 10
// baseline (speedup 1.0000x reference)
#include <cuda_runtime.h>
#include <cuda_bf16.h>

#define N_STEPS   256
#define N_LORS    65536
#define IMG_ELEMS (128*128*128)
#define N_CUBES   (64*64*64)

#define RCP_VOX (1.0f / 2.34375f)
#define VOX     2.34375f

// Image and accumulator in sector-tiled (2x2x2 cube) layout:
// one 32B sector = one 2x2x2 voxel cube. Slot order within cube:
// ((x&1)<<2) | ((y&1)<<1) | (z&1).
__device__ float g_img_cube[IMG_ELEMS];
__device__ float g_acc_cube[IMG_ELEMS];

__device__ __forceinline__ int cube_flat(int ix, int iy, int iz) {
    const int c = (((ix >> 1) << 6) + (iy >> 1)) * 64 + (iz >> 1);
    return (c << 3) + ((ix & 1) << 2) + ((iy & 1) << 1) + (iz & 1);
}

// div.rn(x, VOX) via correctly-rounded reciprocal + one Markstein FMA step
// (matches IEEE division; flip probability <1e-9/coord — see earlier rounds).
__device__ __forceinline__ float div_vox(float x) {
    float q = __fmul_rn(x, RCP_VOX);
    q = __fmaf_rn(__fmaf_rn(-VOX, q, x), RCP_VOX, q);
    return q;
}

// ---------------------------------------------------------------------------
// Kernel 1: coalesced remap image -> cube layout + zero accumulator.
// One thread per 2x2x2 cube: 4 coalesced float2 reads, 2+2 float4 writes.
// ---------------------------------------------------------------------------
__global__ void remap_kernel(const float* __restrict__ img) {
    const int c  = blockIdx.x * blockDim.x + threadIdx.x;   // cube id
    const int cx = c >> 12, cy = (c >> 6) & 63, cz = c & 63;
    const int base = cx * 32768 + cy * 256 + cz * 2;        // natural idx of (2cx,2cy,2cz)

    const float2 a = *(const float2*)(img + base);            // (0,0,z0),(0,0,z1)
    const float2 b = *(const float2*)(img + base + 128);      // (0,1,*)
    const float2 d = *(const float2*)(img + base + 16384);    // (1,0,*)
    const float2 e = *(const float2*)(img + base + 16384 + 128); // (1,1,*)

    float4* dst = (float4*)(g_img_cube + (c << 3));
    dst[0] = make_float4(a.x, a.y, b.x, b.y);
    dst[1] = make_float4(d.x, d.y, e.x, e.y);

    float4* az = (float4*)(g_acc_cube + (c << 3));
    az[0] = make_float4(0.f, 0.f, 0.f, 0.f);
    az[1] = make_float4(0.f, 0.f, 0.f, 0.f);
}

// ---------------------------------------------------------------------------
// Kernel 2: warp-per-LOR, lane = consecutive step within each 32-step chunk.
//   Forward: 8 independent gathers (cube layout -> few sectors per warp-load).
//   Backward: one scalar 4B RED per same-voxel run, with runs CARRIED across
//             iteration boundaries (no split atomics).
// ---------------------------------------------------------------------------
__global__ __launch_bounds__(256)
void trace_kernel(const float* __restrict__ xl,
                  const float* __restrict__ yl,
                  const float* __restrict__ zl) {
    const int warp = blockIdx.x * (blockDim.x >> 5) + (threadIdx.x >> 5);
    const int lane = threadIdx.x & 31;
    const int set  = warp >> 16;          // 0,1,2
    const int lor  = warp & (N_LORS - 1);

    const float* lors = (set == 0) ? xl : (set == 1) ? yl : zl;
    const float* L = lors + 7 * lor;

    const float p1x = __ldg(L + 0), p1y = __ldg(L + 1), p1z = __ldg(L + 2);
    const float dx = __fadd_rn(__ldg(L + 3), -p1x);
    const float dy = __fadd_rn(__ldg(L + 4), -p1y);
    const float dz = __fadd_rn(__ldg(L + 5), -p1z);
    const float meas = __ldg(L + 6);
    const float seg = sqrtf(dx*dx + dy*dy + dz*dz) * (1.0f / N_STEPS);

    int flats[8];

    // exact: all t are multiples of 2^-9
    float t = ((float)lane + 0.5f) * (1.0f / N_STEPS);

    #pragma unroll
    for (int it = 0; it < 8; it++) {
        const float px = __fadd_rn(p1x, __fmul_rn(t, dx));
        const float py = __fadd_rn(p1y, __fmul_rn(t, dy));
        const float pz = __fadd_rn(p1z, __fmul_rn(t, dz));
        const int ix = __float2int_rd(div_vox(__fadd_rn(px, 150.0f)));
        const int iy = __float2int_rd(div_vox(__fadd_rn(py, 150.0f)));
        const int iz = __float2int_rd(div_vox(__fadd_rn(pz, 150.0f)));
        const bool inb = ((unsigned)ix < 128u) & ((unsigned)iy < 128u) &
                         ((unsigned)iz < 128u);
        flats[it] = inb ? cube_flat(ix, iy, iz) : -1;
        t = __fadd_rn(t, 0.125f);
    }

    // ---- forward projection: 8 independent gathers ----
    float s = 0.f;
    #pragma unroll
    for (int it = 0; it < 8; it++) {
        const int f = flats[it];
        s += (f >= 0) ? __ldg(g_img_cube + f) : 0.f;
    }

    #pragma unroll
    for (int o = 16; o > 0; o >>= 1)
        s += __shfl_xor_sync(0xffffffffu, s, o);

    const float proj = s * seg;
    const float w = meas / (proj + 1e-8f) * seg;   // ratio * seg

    // ---- backprojection: runs carried across iteration boundaries ----
    int carry_flat = -1;     // warp-uniform: flat of the open tail run
    int carry_cnt  = 0;      // steps accumulated in the open tail run
    #pragma unroll
    for (int it = 0; it < 8; it++) {
        const int f = flats[it];
        const int fprev = __shfl_up_sync(0xffffffffu, f, 1);
        const bool head = (lane == 0) ? (f != carry_flat) : (f != fprev);
        const unsigned b = __ballot_sync(0xffffffffu, head);
        if (b == 0u) {                 // whole chunk continues the carry run
            carry_cnt += 32;
            continue;
        }
        const int first_head = __ffs(b) - 1;
        // close the carried run (absorbs initial continuation segment)
        if (lane == 0 && carry_flat >= 0)
            atomicAdd(g_acc_cube + carry_flat, w * (float)(carry_cnt + first_head));
        // middle runs: every head except the last emits
        const unsigned rest = (b >> lane) >> 1;      // heads after me
        if (head && f >= 0 && rest != 0u)
            atomicAdd(g_acc_cube + f, w * (float)__ffs(rest));
        // tail run becomes the new carry
        const int last_head = 31 - __clz(b);
        carry_flat = __shfl_sync(0xffffffffu, f, 31);
        carry_cnt  = 32 - last_head;
    }
    if (lane == 0 && carry_flat >= 0)
        atomicAdd(g_acc_cube + carry_flat, w * (float)carry_cnt);
}

// ---------------------------------------------------------------------------
// Kernel 3: out = image / (eff + eps) * acc.  One thread per cube:
// coalesced float4 acc reads, float2 img/eff/out accesses.
// ---------------------------------------------------------------------------
__global__ void finalize_kernel(const float* __restrict__ img,
                                const float* __restrict__ eff,
                                float* __restrict__ out) {
    const int c  = blockIdx.x * blockDim.x + threadIdx.x;   // cube id
    const int cx = c >> 12, cy = (c >> 6) & 63, cz = c & 63;
    const int base = cx * 32768 + cy * 256 + cz * 2;

    const float4* av = (const float4*)(g_acc_cube + (c << 3));
    const float4 a0 = av[0];   // slots 0..3: (0,0,z0)(0,0,z1)(0,1,z0)(0,1,z1)
    const float4 a1 = av[1];   // slots 4..7: (1,0,z0)(1,0,z1)(1,1,z0)(1,1,z1)

    #pragma unroll
    for (int k = 0; k < 4; k++) {
        const int off = ((k >> 1) ? 16384 : 0) + ((k & 1) ? 128 : 0);
        const float2 im = *(const float2*)(img + base + off);
        const float2 ef = *(const float2*)(eff + base + off);
        const float ax = (k == 0) ? a0.x : (k == 1) ? a0.z : (k == 2) ? a1.x : a1.z;
        const float ay = (k == 0) ? a0.y : (k == 1) ? a0.w : (k == 2) ? a1.y : a1.w;
        float2 o;
        o.x = im.x / (ef.x + 1e-8f) * ax;
        o.y = im.y / (ef.y + 1e-8f) * ay;
        *(float2*)(out + base + off) = o;
    }
}

extern "C" void kernel_launch(void* const* d_in, const int* in_sizes, int n_in,
                              void* d_out, int out_size) {
    const float* image = (const float*)d_in[0];
    const float* eff   = (const float*)d_in[1];
    const float* xl    = (const float*)d_in[2];
    const float* yl    = (const float*)d_in[3];
    const float* zl    = (const float*)d_in[4];
    float* out = (float*)d_out;

    remap_kernel<<<N_CUBES / 256, 256>>>(image);

    const int total_warps = 3 * N_LORS;          // one warp per LOR
    trace_kernel<<<total_warps / 8, 256>>>(xl, yl, zl);

    finalize_kernel<<<N_CUBES / 256, 256>>>(image, eff, out);
}

// round 11
// speedup vs baseline: 1.2139x; 1.2139x over previous
#include <cuda_runtime.h>
#include <cuda_bf16.h>

#define N_STEPS   256
#define N_LORS    65536
#define IMG_ELEMS (128*128*128)
#define N_CUBES   (64*64*64)

#define RCP_VOX (1.0f / 2.34375f)
#define VOX     2.34375f

// Image and accumulator in sector-tiled (2x2x2 cube) layout:
// one 32B sector = one 2x2x2 voxel cube. Slot order within cube:
// ((x&1)<<2) | ((y&1)<<1) | (z&1).
__device__ float g_img_cube[IMG_ELEMS];
__device__ float g_acc_cube[IMG_ELEMS];

__device__ __forceinline__ int cube_flat(int ix, int iy, int iz) {
    const int c = (((ix >> 1) << 6) + (iy >> 1)) * 64 + (iz >> 1);
    return (c << 3) + ((ix & 1) << 2) + ((iy & 1) << 1) + (iz & 1);
}

// div.rn(x, VOX) via correctly-rounded reciprocal + one Markstein FMA step
// (matches IEEE division; flip probability <1e-9/coord — see earlier rounds).
__device__ __forceinline__ float div_vox(float x) {
    float q = __fmul_rn(x, RCP_VOX);
    q = __fmaf_rn(__fmaf_rn(-VOX, q, x), RCP_VOX, q);
    return q;
}

// ---------------------------------------------------------------------------
// Kernel 1: coalesced remap image -> cube layout + zero accumulator.
// One thread per 2x2x2 cube: 4 coalesced float2 reads, 2+2 float4 writes.
// ---------------------------------------------------------------------------
__global__ void remap_kernel(const float* __restrict__ img) {
    const int c  = blockIdx.x * blockDim.x + threadIdx.x;   // cube id
    const int cx = c >> 12, cy = (c >> 6) & 63, cz = c & 63;
    const int base = cx * 32768 + cy * 256 + cz * 2;        // natural idx of (2cx,2cy,2cz)

    const float2 a = *(const float2*)(img + base);               // (0,0,*)
    const float2 b = *(const float2*)(img + base + 128);         // (0,1,*)
    const float2 d = *(const float2*)(img + base + 16384);       // (1,0,*)
    const float2 e = *(const float2*)(img + base + 16384 + 128); // (1,1,*)

    float4* dst = (float4*)(g_img_cube + (c << 3));
    dst[0] = make_float4(a.x, a.y, b.x, b.y);
    dst[1] = make_float4(d.x, d.y, e.x, e.y);

    float4* az = (float4*)(g_acc_cube + (c << 3));
    az[0] = make_float4(0.f, 0.f, 0.f, 0.f);
    az[1] = make_float4(0.f, 0.f, 0.f, 0.f);
}

// ---------------------------------------------------------------------------
// Kernel 2: warp-per-LOR, lane = consecutive step within each 32-step chunk.
//   (r9 body — best measured. No cross-iteration carry: iterations stay
//    independent; one predicated 4B RED per contiguous same-voxel run.)
// ---------------------------------------------------------------------------
__global__ __launch_bounds__(256)
void trace_kernel(const float* __restrict__ xl,
                  const float* __restrict__ yl,
                  const float* __restrict__ zl) {
    const int warp = blockIdx.x * (blockDim.x >> 5) + (threadIdx.x >> 5);
    const int lane = threadIdx.x & 31;
    const int set  = warp >> 16;          // 0,1,2
    const int lor  = warp & (N_LORS - 1);

    const float* lors = (set == 0) ? xl : (set == 1) ? yl : zl;
    const float* L = lors + 7 * lor;

    const float p1x = __ldg(L + 0), p1y = __ldg(L + 1), p1z = __ldg(L + 2);
    const float dx = __fadd_rn(__ldg(L + 3), -p1x);
    const float dy = __fadd_rn(__ldg(L + 4), -p1y);
    const float dz = __fadd_rn(__ldg(L + 5), -p1z);
    const float meas = __ldg(L + 6);
    const float seg = sqrtf(dx*dx + dy*dy + dz*dz) * (1.0f / N_STEPS);

    int flats[8];

    // exact: all t are multiples of 2^-9
    float t = ((float)lane + 0.5f) * (1.0f / N_STEPS);

    #pragma unroll
    for (int it = 0; it < 8; it++) {
        const float px = __fadd_rn(p1x, __fmul_rn(t, dx));
        const float py = __fadd_rn(p1y, __fmul_rn(t, dy));
        const float pz = __fadd_rn(p1z, __fmul_rn(t, dz));
        const int ix = __float2int_rd(div_vox(__fadd_rn(px, 150.0f)));
        const int iy = __float2int_rd(div_vox(__fadd_rn(py, 150.0f)));
        const int iz = __float2int_rd(div_vox(__fadd_rn(pz, 150.0f)));
        const bool inb = ((unsigned)ix < 128u) & ((unsigned)iy < 128u) &
                         ((unsigned)iz < 128u);
        flats[it] = inb ? cube_flat(ix, iy, iz) : -1;
        t = __fadd_rn(t, 0.125f);
    }

    // ---- forward projection: 8 independent gathers ----
    float s = 0.f;
    #pragma unroll
    for (int it = 0; it < 8; it++) {
        const int f = flats[it];
        s += (f >= 0) ? __ldg(g_img_cube + f) : 0.f;
    }

    #pragma unroll
    for (int o = 16; o > 0; o >>= 1)
        s += __shfl_xor_sync(0xffffffffu, s, o);

    const float proj = s * seg;
    const float w = meas / (proj + 1e-8f) * seg;   // ratio * seg

    // ---- backprojection: one scalar atomic per contiguous same-voxel run --
    #pragma unroll
    for (int it = 0; it < 8; it++) {
        const int f = flats[it];
        const int fprev = __shfl_up_sync(0xffffffffu, f, 1);
        const bool head = (lane == 0) || (f != fprev);
        const unsigned b = __ballot_sync(0xffffffffu, head);
        if (head && f >= 0) {
            const unsigned rest = (b >> lane) >> 1;   // heads after me
            const int cnt = rest ? __ffs(rest) : (32 - lane);
            atomicAdd(g_acc_cube + f, w * (float)cnt);
        }
    }
}

// ---------------------------------------------------------------------------
// Kernel 3: out = image / (eff + eps) * acc.  One thread per cube:
// coalesced float4 acc reads, float2 img/eff/out accesses.
// ---------------------------------------------------------------------------
__global__ void finalize_kernel(const float* __restrict__ img,
                                const float* __restrict__ eff,
                                float* __restrict__ out) {
    const int c  = blockIdx.x * blockDim.x + threadIdx.x;   // cube id
    const int cx = c >> 12, cy = (c >> 6) & 63, cz = c & 63;
    const int base = cx * 32768 + cy * 256 + cz * 2;

    const float4* av = (const float4*)(g_acc_cube + (c << 3));
    const float4 a0 = av[0];   // slots 0..3: (0,0,z0)(0,0,z1)(0,1,z0)(0,1,z1)
    const float4 a1 = av[1];   // slots 4..7: (1,0,z0)(1,0,z1)(1,1,z0)(1,1,z1)

    #pragma unroll
    for (int k = 0; k < 4; k++) {
        const int off = ((k >> 1) ? 16384 : 0) + ((k & 1) ? 128 : 0);
        const float2 im = *(const float2*)(img + base + off);
        const float2 ef = *(const float2*)(eff + base + off);
        const float ax = (k == 0) ? a0.x : (k == 1) ? a0.z : (k == 2) ? a1.x : a1.z;
        const float ay = (k == 0) ? a0.y : (k == 1) ? a0.w : (k == 2) ? a1.y : a1.w;
        float2 o;
        o.x = im.x / (ef.x + 1e-8f) * ax;
        o.y = im.y / (ef.y + 1e-8f) * ay;
        *(float2*)(out + base + off) = o;
    }
}

extern "C" void kernel_launch(void* const* d_in, const int* in_sizes, int n_in,
                              void* d_out, int out_size) {
    const float* image = (const float*)d_in[0];
    const float* eff   = (const float*)d_in[1];
    const float* xl    = (const float*)d_in[2];
    const float* yl    = (const float*)d_in[3];
    const float* zl    = (const float*)d_in[4];
    float* out = (float*)d_out;

    remap_kernel<<<N_CUBES / 256, 256>>>(image);

    const int total_warps = 3 * N_LORS;          // one warp per LOR
    trace_kernel<<<total_warps / 8, 256>>>(xl, yl, zl);

    finalize_kernel<<<N_CUBES / 256, 256>>>(image, eff, out);
}